// round 1
// baseline (speedup 1.0000x reference)
#include <cuda_runtime.h>

// Problem constants
#define HDIM   1024
#define DIN    256
#define DOUT   256
#define BATCH  8192
#define NLAYERS 64

// Ping-pong activation buffers, stored in "m = 2*h - 1" form (ready as GEMM input).
__device__ float g_act[2][HDIM * BATCH];

enum { MODE_EXP = 0, MODE_HID = 1, MODE_OUT = 2 };

// C = op( A[M,K] @ B[K,N] )  with mode-specific input/epilogue fusion.
//  MODE_EXP: B elements transformed 2b-1 on load; epilogue m = 2*clip(y,0,1)-1
//  MODE_HID: epilogue y += B[row,col] (residual, M==K), then m = 2*clip(y,0,1)-1
//  MODE_OUT: epilogue clip(y,0,1)
template <int MODE>
__global__ __launch_bounds__(256)
void gemm_kernel(const float* __restrict__ A, const float* __restrict__ Bm,
                 float* __restrict__ C, int M, int N, int K)
{
    constexpr int BM = 128, BN = 128, BK = 16, TM = 8, TN = 8;
    __shared__ float As[2][BK][BM];
    __shared__ float Bs[2][BK][BN];

    const int tid = threadIdx.x;
    const int m0 = blockIdx.y * BM;
    const int n0 = blockIdx.x * BN;
    const int tx = tid & 15;      // n direction (x8)
    const int ty = tid >> 4;      // m direction (x8)

    // Global-load index mapping (512 float4 per tile per matrix, 2 per thread)
    const int a_row = tid >> 2;           // 0..63  (+256 -> 64..127)
    const int a_k4  = (tid & 3) * 4;      // 0,4,8,12
    const int b_row = tid >> 5;           // 0..7   (+256 -> 8..15)
    const int b_c4  = (tid & 31) * 4;     // 0..124

    float acc[TM][TN];
    #pragma unroll
    for (int i = 0; i < TM; i++)
        #pragma unroll
        for (int j = 0; j < TN; j++) acc[i][j] = 0.0f;

    const int ntiles = K / BK;

    // ---- initial tile -> buffer 0 ----
    #pragma unroll
    for (int s = 0; s < 2; s++) {
        int ar = a_row + s * 64;
        float4 va = *(const float4*)(A + (size_t)(m0 + ar) * K + a_k4);
        As[0][a_k4 + 0][ar] = va.x;
        As[0][a_k4 + 1][ar] = va.y;
        As[0][a_k4 + 2][ar] = va.z;
        As[0][a_k4 + 3][ar] = va.w;

        int br = b_row + s * 8;
        float4 vb = *(const float4*)(Bm + (size_t)br * N + n0 + b_c4);
        if (MODE == MODE_EXP) {
            vb.x = 2.0f * vb.x - 1.0f; vb.y = 2.0f * vb.y - 1.0f;
            vb.z = 2.0f * vb.z - 1.0f; vb.w = 2.0f * vb.w - 1.0f;
        }
        *(float4*)&Bs[0][br][b_c4] = vb;
    }
    __syncthreads();

    for (int t = 0; t < ntiles; t++) {
        const int cur = t & 1;
        const int nxt = cur ^ 1;

        float4 pa[2], pb[2];
        const bool has_next = (t + 1) < ntiles;
        if (has_next) {
            const int kbase = (t + 1) * BK;
            #pragma unroll
            for (int s = 0; s < 2; s++) {
                int ar = a_row + s * 64;
                pa[s] = *(const float4*)(A + (size_t)(m0 + ar) * K + kbase + a_k4);
                int br = b_row + s * 8;
                pb[s] = *(const float4*)(Bm + (size_t)(kbase + br) * N + n0 + b_c4);
            }
        }

        #pragma unroll
        for (int k = 0; k < BK; k++) {
            float a[TM], b[TN];
            *(float4*)&a[0] = *(const float4*)&As[cur][k][ty * TM];
            *(float4*)&a[4] = *(const float4*)&As[cur][k][ty * TM + 4];
            *(float4*)&b[0] = *(const float4*)&Bs[cur][k][tx * TN];
            *(float4*)&b[4] = *(const float4*)&Bs[cur][k][tx * TN + 4];
            #pragma unroll
            for (int i = 0; i < TM; i++)
                #pragma unroll
                for (int j = 0; j < TN; j++)
                    acc[i][j] = fmaf(a[i], b[j], acc[i][j]);
        }

        if (has_next) {
            #pragma unroll
            for (int s = 0; s < 2; s++) {
                int ar = a_row + s * 64;
                As[nxt][a_k4 + 0][ar] = pa[s].x;
                As[nxt][a_k4 + 1][ar] = pa[s].y;
                As[nxt][a_k4 + 2][ar] = pa[s].z;
                As[nxt][a_k4 + 3][ar] = pa[s].w;
                int br = b_row + s * 8;
                float4 vb = pb[s];
                if (MODE == MODE_EXP) {
                    vb.x = 2.0f * vb.x - 1.0f; vb.y = 2.0f * vb.y - 1.0f;
                    vb.z = 2.0f * vb.z - 1.0f; vb.w = 2.0f * vb.w - 1.0f;
                }
                *(float4*)&Bs[nxt][br][b_c4] = vb;
            }
            __syncthreads();
        }
    }

    // ---- epilogue ----
    #pragma unroll
    for (int i = 0; i < TM; i++) {
        const int row = m0 + ty * TM + i;
        #pragma unroll
        for (int j4 = 0; j4 < 2; j4++) {
            const int col = n0 + tx * TN + j4 * 4;
            float y[4];
            y[0] = acc[i][j4 * 4 + 0];
            y[1] = acc[i][j4 * 4 + 1];
            y[2] = acc[i][j4 * 4 + 2];
            y[3] = acc[i][j4 * 4 + 3];
            if (MODE == MODE_HID) {
                float4 r = *(const float4*)(Bm + (size_t)row * N + col);
                y[0] += r.x; y[1] += r.y; y[2] += r.z; y[3] += r.w;
            }
            float4 o;
            #pragma unroll
            for (int q = 0; q < 4; q++) {
                float v = fminf(fmaxf(y[q], 0.0f), 1.0f);
                if (MODE != MODE_OUT) v = 2.0f * v - 1.0f;
                ((float*)&o)[q] = v;
            }
            *(float4*)(C + (size_t)row * N + col) = o;
        }
    }
}

extern "C" void kernel_launch(void* const* d_in, const int* in_sizes, int n_in,
                              void* d_out, int out_size)
{
    const float* x           = (const float*)d_in[0]; // [DIN, BATCH]
    const float* expansion   = (const float*)d_in[1]; // [HDIM, DIN]
    const float* hidden      = (const float*)d_in[2]; // [NLAYERS, HDIM, HDIM]
    const float* compression = (const float*)d_in[3]; // [DOUT, HDIM]
    float* out = (float*)d_out;                        // [DOUT, BATCH]

    float* act0 = nullptr;
    cudaGetSymbolAddress((void**)&act0, g_act);
    float* act1 = act0 + (size_t)HDIM * BATCH;

    dim3 blk(256);

    // Expansion: m0 = 2*clip(E @ (2x-1)) - 1
    gemm_kernel<MODE_EXP><<<dim3(BATCH / 128, HDIM / 128), blk>>>(
        expansion, x, act0, HDIM, BATCH, DIN);

    // 64 hidden layers: m' = 2*clip(W m + m) - 1
    float* cur = act0;
    float* nxt = act1;
    for (int l = 0; l < NLAYERS; l++) {
        gemm_kernel<MODE_HID><<<dim3(BATCH / 128, HDIM / 128), blk>>>(
            hidden + (size_t)l * HDIM * HDIM, cur, nxt, HDIM, BATCH, HDIM);
        float* tmp = cur; cur = nxt; nxt = tmp;
    }

    // Compression: out = clip(Cmp @ m)
    gemm_kernel<MODE_OUT><<<dim3(BATCH / 128, DOUT / 128), blk>>>(
        compression, cur, out, DOUT, BATCH, HDIM);
}

// round 5
// speedup vs baseline: 1.1633x; 1.1633x over previous
#include <cuda_runtime.h>
#include <cstdint>

// Problem constants
#define HDIM   1024
#define DIN    256
#define DOUT   256
#define BATCH  8192
#define NLAYERS 64

// Ping-pong activation buffers, stored in "m = 2*h - 1" form (ready as GEMM input).
__device__ float g_act[2][HDIM * BATCH];

enum { MODE_EXP = 0, MODE_HID = 1, MODE_OUT = 2 };

typedef unsigned long long u64;

__device__ __forceinline__ u64 pack2(float lo, float hi) {
    u64 r;
    asm("mov.b64 %0, {%1, %2};" : "=l"(r) : "f"(lo), "f"(hi));
    return r;
}
__device__ __forceinline__ void unpack2(u64 v, float& lo, float& hi) {
    asm("mov.b64 {%0, %1}, %2;" : "=f"(lo), "=f"(hi) : "l"(v));
}
// packed dual IEEE-RN fp32 fma: d.lo = a.lo*b.lo + c.lo ; d.hi = a.hi*b.hi + c.hi
__device__ __forceinline__ u64 fma2(u64 a, u64 b, u64 c) {
    u64 d;
    asm("fma.rn.f32x2 %0, %1, %2, %3;" : "=l"(d) : "l"(a), "l"(b), "l"(c));
    return d;
}

// C = op( A[M,K] @ B[K,N] )  with mode-specific input/epilogue fusion.
//  MODE_EXP: B elements transformed 2b-1 on load; epilogue m = 2*clip(y,0,1)-1
//  MODE_HID: epilogue y += B[row,col] (residual, M==K), then m = 2*clip(y,0,1)-1
//  MODE_OUT: epilogue clip(y,0,1)
template <int MODE>
__global__ __launch_bounds__(256, 2)
void gemm_kernel(const float* __restrict__ A, const float* __restrict__ Bm,
                 float* __restrict__ C, int M, int N, int K)
{
    constexpr int BM = 128, BN = 128, BK = 16, TM = 8;
    __shared__ float As[2][BK][BM];
    __shared__ float Bs[2][BK][BN];

    const int tid = threadIdx.x;
    const int m0 = blockIdx.y * BM;
    const int n0 = blockIdx.x * BN;
    const int tx = tid & 15;      // n direction (x8)
    const int ty = tid >> 4;      // m direction (x8)

    // Global-load index mapping (512 float4 per tile per matrix, 2 per thread)
    const int a_row = tid >> 2;           // 0..63  (+256 -> 64..127)
    const int a_k4  = (tid & 3) * 4;      // 0,4,8,12
    const int b_row = tid >> 5;           // 0..7   (+256 -> 8..15)
    const int b_c4  = (tid & 31) * 4;     // 0..124

    // accumulators: 8 rows x 4 column-pairs, each u64 = (col even, col odd)
    u64 acc2[TM][4];
    const u64 z2 = pack2(0.0f, 0.0f);
    #pragma unroll
    for (int i = 0; i < TM; i++)
        #pragma unroll
        for (int jp = 0; jp < 4; jp++) acc2[i][jp] = z2;

    const int ntiles = K / BK;

    // ---- initial tile -> buffer 0 ----
    #pragma unroll
    for (int s = 0; s < 2; s++) {
        int ar = a_row + s * 64;
        float4 va = *(const float4*)(A + (size_t)(m0 + ar) * K + a_k4);
        As[0][a_k4 + 0][ar] = va.x;
        As[0][a_k4 + 1][ar] = va.y;
        As[0][a_k4 + 2][ar] = va.z;
        As[0][a_k4 + 3][ar] = va.w;

        int br = b_row + s * 8;
        float4 vb = *(const float4*)(Bm + (size_t)br * N + n0 + b_c4);
        if (MODE == MODE_EXP) {
            vb.x = 2.0f * vb.x - 1.0f; vb.y = 2.0f * vb.y - 1.0f;
            vb.z = 2.0f * vb.z - 1.0f; vb.w = 2.0f * vb.w - 1.0f;
        }
        *(float4*)&Bs[0][br][b_c4] = vb;
    }
    __syncthreads();

    for (int t = 0; t < ntiles; t++) {
        const int cur = t & 1;
        const int nxt = cur ^ 1;

        float4 pa[2], pb[2];
        const bool has_next = (t + 1) < ntiles;
        if (has_next) {
            const int kbase = (t + 1) * BK;
            #pragma unroll
            for (int s = 0; s < 2; s++) {
                int ar = a_row + s * 64;
                pa[s] = *(const float4*)(A + (size_t)(m0 + ar) * K + kbase + a_k4);
                int br = b_row + s * 8;
                pb[s] = *(const float4*)(Bm + (size_t)(kbase + br) * N + n0 + b_c4);
            }
        }

        #pragma unroll
        for (int k = 0; k < BK; k++) {
            float a[TM];
            float4 b0 = *(const float4*)&Bs[cur][k][tx * 8];
            float4 b1 = *(const float4*)&Bs[cur][k][tx * 8 + 4];
            *(float4*)&a[0] = *(const float4*)&As[cur][k][ty * TM];
            *(float4*)&a[4] = *(const float4*)&As[cur][k][ty * TM + 4];

            // column pairs (adjacent registers from the float4 loads)
            u64 bp[4];
            bp[0] = pack2(b0.x, b0.y);
            bp[1] = pack2(b0.z, b0.w);
            bp[2] = pack2(b1.x, b1.y);
            bp[3] = pack2(b1.z, b1.w);

            #pragma unroll
            for (int i = 0; i < TM; i++) {
                const u64 aa = pack2(a[i], a[i]);   // broadcast (ALU pipe)
                #pragma unroll
                for (int jp = 0; jp < 4; jp++)
                    acc2[i][jp] = fma2(aa, bp[jp], acc2[i][jp]);
            }
        }

        if (has_next) {
            #pragma unroll
            for (int s = 0; s < 2; s++) {
                int ar = a_row + s * 64;
                As[nxt][a_k4 + 0][ar] = pa[s].x;
                As[nxt][a_k4 + 1][ar] = pa[s].y;
                As[nxt][a_k4 + 2][ar] = pa[s].z;
                As[nxt][a_k4 + 3][ar] = pa[s].w;
                int br = b_row + s * 8;
                float4 vb = pb[s];
                if (MODE == MODE_EXP) {
                    vb.x = 2.0f * vb.x - 1.0f; vb.y = 2.0f * vb.y - 1.0f;
                    vb.z = 2.0f * vb.z - 1.0f; vb.w = 2.0f * vb.w - 1.0f;
                }
                *(float4*)&Bs[nxt][br][b_c4] = vb;
            }
            __syncthreads();
        }
    }

    // ---- epilogue ----
    #pragma unroll
    for (int i = 0; i < TM; i++) {
        const int row = m0 + ty * TM + i;
        #pragma unroll
        for (int j4 = 0; j4 < 2; j4++) {
            const int col = n0 + tx * 8 + j4 * 4;
            float y[4];
            unpack2(acc2[i][j4 * 2 + 0], y[0], y[1]);
            unpack2(acc2[i][j4 * 2 + 1], y[2], y[3]);
            if (MODE == MODE_HID) {
                float4 r = *(const float4*)(Bm + (size_t)row * N + col);
                y[0] += r.x; y[1] += r.y; y[2] += r.z; y[3] += r.w;
            }
            float4 o;
            #pragma unroll
            for (int q = 0; q < 4; q++) {
                float v = fminf(fmaxf(y[q], 0.0f), 1.0f);
                if (MODE != MODE_OUT) v = 2.0f * v - 1.0f;
                ((float*)&o)[q] = v;
            }
            *(float4*)(C + (size_t)row * N + col) = o;
        }
    }
}

extern "C" void kernel_launch(void* const* d_in, const int* in_sizes, int n_in,
                              void* d_out, int out_size)
{
    const float* x           = (const float*)d_in[0]; // [DIN, BATCH]
    const float* expansion   = (const float*)d_in[1]; // [HDIM, DIN]
    const float* hidden      = (const float*)d_in[2]; // [NLAYERS, HDIM, HDIM]
    const float* compression = (const float*)d_in[3]; // [DOUT, HDIM]
    float* out = (float*)d_out;                        // [DOUT, BATCH]

    float* act0 = nullptr;
    cudaGetSymbolAddress((void**)&act0, g_act);
    float* act1 = act0 + (size_t)HDIM * BATCH;

    dim3 blk(256);

    // Expansion: m0 = 2*clip(E @ (2x-1)) - 1
    gemm_kernel<MODE_EXP><<<dim3(BATCH / 128, HDIM / 128), blk>>>(
        expansion, x, act0, HDIM, BATCH, DIN);

    // 64 hidden layers: m' = 2*clip(W m + m) - 1
    float* cur = act0;
    float* nxt = act1;
    for (int l = 0; l < NLAYERS; l++) {
        gemm_kernel<MODE_HID><<<dim3(BATCH / 128, HDIM / 128), blk>>>(
            hidden + (size_t)l * HDIM * HDIM, cur, nxt, HDIM, BATCH, HDIM);
        float* tmp = cur; cur = nxt; nxt = tmp;
    }

    // Compression: out = clip(Cmp @ m)
    gemm_kernel<MODE_OUT><<<dim3(BATCH / 128, DOUT / 128), blk>>>(
        compression, cur, out, DOUT, BATCH, HDIM);
}